// round 11
// baseline (speedup 1.0000x reference)
#include <cuda_runtime.h>

#define N_NODES 320000
#define F_IN    128
#define L       10
#define CAP     80
#define N_EDGES 10240000
#define FULL    0xffffffffu

static __device__ int    g_cnt[N_NODES];
static __device__ float  g_dis[N_NODES];
static __device__ float4 g_hwA[(size_t)N_NODES * 4];   // 16-float padded rows (64B)
static __device__ float4 g_hwB[(size_t)N_NODES * 4];
static __device__ float4 g_agg[(size_t)N_NODES * 4];   // gather results
static __device__ int    g_csr[(size_t)N_NODES * CAP];

// ---------------------------------------------------------------------------
// 1) Bucket scatter (1 edge/thread, round-8 proven form)
// ---------------------------------------------------------------------------
__global__ void k_scatter(const int* __restrict__ ei) {
    int e = blockIdx.x * blockDim.x + threadIdx.x;
    if (e >= N_EDGES) return;
    int r = ei[e];
    int c = ei[N_EDGES + e];
    int pos = atomicAdd(&g_cnt[c], 1);
    if (pos < CAP) g_csr[(size_t)c * CAP + pos] = r;
}

// ---------------------------------------------------------------------------
// 2) Input (graph-independent, overlapped with scatter):
//    hwA[n] = relu(x@Win + bin) @ W1   (UNSCALED)
// ---------------------------------------------------------------------------
__global__ void k_input(const float* __restrict__ x, const float* __restrict__ Win,
                        const float* __restrict__ bin, const float* __restrict__ W1) {
    __shared__ float sW[F_IN * L];
    __shared__ float sB[L];
    __shared__ float sW1[L * L];
    for (int i = threadIdx.x; i < F_IN * L; i += blockDim.x) sW[i] = Win[i];
    for (int i = threadIdx.x; i < L * L;   i += blockDim.x) sW1[i] = W1[i];
    if (threadIdx.x < L) sB[threadIdx.x] = bin[threadIdx.x];
    __syncthreads();

    int t  = blockIdx.x * blockDim.x + threadIdx.x;
    int n0 = 2 * t;
    if (n0 >= N_NODES) return;
    int n1 = n0 + 1;

    float acc0[L], acc1[L];
    #pragma unroll
    for (int j = 0; j < L; j++) { acc0[j] = 0.f; acc1[j] = 0.f; }

    const float4* x0 = (const float4*)(x + (size_t)n0 * F_IN);
    const float4* x1 = (const float4*)(x + (size_t)n1 * F_IN);

    #pragma unroll 4
    for (int kq = 0; kq < F_IN / 4; kq++) {
        float4 a = x0[kq];
        float4 b = x1[kq];
        float va[4] = {a.x, a.y, a.z, a.w};
        float vb[4] = {b.x, b.y, b.z, b.w};
        #pragma unroll
        for (int u = 0; u < 4; u++) {
            int k = kq * 4 + u;
            #pragma unroll
            for (int j = 0; j < L; j++) {
                float w = sW[k * L + j];
                acc0[j] = fmaf(va[u], w, acc0[j]);
                acc1[j] = fmaf(vb[u], w, acc1[j]);
            }
        }
    }

    float h0[L], h1[L];
    #pragma unroll
    for (int j = 0; j < L; j++) {
        h0[j] = fmaxf(acc0[j] + sB[j], 0.f);
        h1[j] = fmaxf(acc1[j] + sB[j], 0.f);
    }

    float t0[L], t1[L];
    #pragma unroll
    for (int j = 0; j < L; j++) { t0[j] = 0.f; t1[j] = 0.f; }
    #pragma unroll
    for (int l = 0; l < L; l++) {
        #pragma unroll
        for (int j = 0; j < L; j++) {
            float w = sW1[l * L + j];
            t0[j] = fmaf(h0[l], w, t0[j]);
            t1[j] = fmaf(h1[l], w, t1[j]);
        }
    }

    float4* o0 = &g_hwA[(size_t)n0 * 4];
    float4* o1 = &g_hwA[(size_t)n1 * 4];
    o0[0] = make_float4(t0[0], t0[1], t0[2], t0[3]);
    o0[1] = make_float4(t0[4], t0[5], t0[6], t0[7]);
    o0[2] = make_float4(t0[8], t0[9], 0.f, 0.f);
    o0[3] = make_float4(0.f, 0.f, 0.f, 0.f);
    o1[0] = make_float4(t1[0], t1[1], t1[2], t1[3]);
    o1[1] = make_float4(t1[4], t1[5], t1[6], t1[7]);
    o1[2] = make_float4(t1[8], t1[9], 0.f, 0.f);
    o1[3] = make_float4(0.f, 0.f, 0.f, 0.f);
}

// ---------------------------------------------------------------------------
// 2b) Join: dis = rsqrt(deg+2); hwA *= dis
// ---------------------------------------------------------------------------
__global__ void k_scale() {
    int i = blockIdx.x * blockDim.x + threadIdx.x;      // float4 index
    if (i >= N_NODES * 4) return;
    int n = i >> 2;
    float dis = rsqrtf((float)g_cnt[n] + 2.0f);
    if ((i & 3) == 0) g_dis[n] = dis;
    float4 v = g_hwA[i];
    v.x *= dis; v.y *= dis; v.z *= dis; v.w *= dis;
    g_hwA[i] = v;
}

// ---------------------------------------------------------------------------
// 3) Pure gather, ONE SINGLE-LINE LDG PER EDGE (no replays):
//    warp/node; whole warp reads one edge's 64B row per LDG (lanes 16-31
//    duplicate lanes 0-15 within the same 128B line -> 1 wavefront).
//    Indices fetched coalesced 32-at-a-time, broadcast via shfl.
//    Lane l accumulates row element (l&15); no butterfly needed.
// ---------------------------------------------------------------------------
__global__ void k_gath(const float* __restrict__ rows) {
    int n = (blockIdx.x * blockDim.x + threadIdx.x) >> 5;
    if (n >= N_NODES) return;
    int lane = threadIdx.x & 31;
    int el   = lane & 15;                    // row element this lane owns

    int cnt = g_cnt[n];
    if (cnt > CAP) cnt = CAP;
    const int* bucket = &g_csr[(size_t)n * CAP];

    float a0 = 0.f, a1 = 0.f;
    for (int base = 0; base < cnt; base += 32) {
        int m = cnt - base;
        if (m > 32) m = 32;
        int idxv = 0;
        if (lane < m) idxv = __ldg(&bucket[base + lane]);   // coalesced batch
        int k = 0;
        for (; k + 1 < m; k += 2) {
            int r0 = __shfl_sync(FULL, idxv, k);
            int r1 = __shfl_sync(FULL, idxv, k + 1);
            float v0 = __ldg(&rows[(size_t)r0 * 16 + el]);  // 1 line, 1 wf
            float v1 = __ldg(&rows[(size_t)r1 * 16 + el]);
            a0 += v0;
            a1 += v1;
        }
        if (k < m) {
            int r = __shfl_sync(FULL, idxv, k);
            a0 += __ldg(&rows[(size_t)r * 16 + el]);
        }
    }
    float acc = a0 + a1;
    if (lane < 16) {                                        // 64B coalesced store
        ((float*)g_agg)[(size_t)n * 16 + lane] = acc;
    }
}

// ---------------------------------------------------------------------------
// 4) Finalize layer 1 (thread/node, coalesced):
//    h = relu(dis*(agg + 2*hwA) + b1);  hwB = dis * (h @ W2)
// ---------------------------------------------------------------------------
__global__ void k_fin1(const float* __restrict__ b1, const float* __restrict__ W2) {
    __shared__ float sW[L * L];
    __shared__ float sB[L];
    for (int i = threadIdx.x; i < L * L; i += blockDim.x) sW[i] = W2[i];
    if (threadIdx.x < L) sB[threadIdx.x] = b1[threadIdx.x];
    __syncthreads();

    int n = blockIdx.x * blockDim.x + threadIdx.x;
    if (n >= N_NODES) return;

    float dis = g_dis[n];
    const float4* ag = &g_agg[(size_t)n * 4];
    const float4* hw = &g_hwA[(size_t)n * 4];
    float4 a0 = ag[0], a1 = ag[1], a2 = ag[2];
    float4 s0 = hw[0], s1 = hw[1], s2 = hw[2];

    float h[L];
    h[0] = fmaxf(dis * (a0.x + 2.f * s0.x) + sB[0], 0.f);
    h[1] = fmaxf(dis * (a0.y + 2.f * s0.y) + sB[1], 0.f);
    h[2] = fmaxf(dis * (a0.z + 2.f * s0.z) + sB[2], 0.f);
    h[3] = fmaxf(dis * (a0.w + 2.f * s0.w) + sB[3], 0.f);
    h[4] = fmaxf(dis * (a1.x + 2.f * s1.x) + sB[4], 0.f);
    h[5] = fmaxf(dis * (a1.y + 2.f * s1.y) + sB[5], 0.f);
    h[6] = fmaxf(dis * (a1.z + 2.f * s1.z) + sB[6], 0.f);
    h[7] = fmaxf(dis * (a1.w + 2.f * s1.w) + sB[7], 0.f);
    h[8] = fmaxf(dis * (a2.x + 2.f * s2.x) + sB[8], 0.f);
    h[9] = fmaxf(dis * (a2.y + 2.f * s2.y) + sB[9], 0.f);

    float t[L];
    #pragma unroll
    for (int j = 0; j < L; j++) t[j] = 0.f;
    #pragma unroll
    for (int l = 0; l < L; l++) {
        #pragma unroll
        for (int j = 0; j < L; j++)
            t[j] = fmaf(h[l], sW[l * L + j], t[j]);
    }

    float4* o = &g_hwB[(size_t)n * 4];
    o[0] = make_float4(dis*t[0], dis*t[1], dis*t[2], dis*t[3]);
    o[1] = make_float4(dis*t[4], dis*t[5], dis*t[6], dis*t[7]);
    o[2] = make_float4(dis*t[8], dis*t[9], 0.f, 0.f);
    o[3] = make_float4(0.f, 0.f, 0.f, 0.f);
}

// ---------------------------------------------------------------------------
// 5) Finalize layer 2 + output:
//    out = relu(dis*(agg + 2*hwB) + b2) @ Wout + bout
// ---------------------------------------------------------------------------
__global__ void k_fin2(const float* __restrict__ b2, const float* __restrict__ Wout,
                       const float* __restrict__ bout, float* __restrict__ out) {
    __shared__ float sWo[L];
    __shared__ float sB[L];
    __shared__ float sb0;
    if (threadIdx.x < L) { sWo[threadIdx.x] = Wout[threadIdx.x]; sB[threadIdx.x] = b2[threadIdx.x]; }
    if (threadIdx.x == 0) sb0 = bout[0];
    __syncthreads();

    int n = blockIdx.x * blockDim.x + threadIdx.x;
    if (n >= N_NODES) return;

    float dis = g_dis[n];
    const float4* ag = &g_agg[(size_t)n * 4];
    const float4* hw = &g_hwB[(size_t)n * 4];
    float4 a0 = ag[0], a1 = ag[1], a2 = ag[2];
    float4 s0 = hw[0], s1 = hw[1], s2 = hw[2];

    float acc = sb0;
    acc = fmaf(fmaxf(dis * (a0.x + 2.f * s0.x) + sB[0], 0.f), sWo[0], acc);
    acc = fmaf(fmaxf(dis * (a0.y + 2.f * s0.y) + sB[1], 0.f), sWo[1], acc);
    acc = fmaf(fmaxf(dis * (a0.z + 2.f * s0.z) + sB[2], 0.f), sWo[2], acc);
    acc = fmaf(fmaxf(dis * (a0.w + 2.f * s0.w) + sB[3], 0.f), sWo[3], acc);
    acc = fmaf(fmaxf(dis * (a1.x + 2.f * s1.x) + sB[4], 0.f), sWo[4], acc);
    acc = fmaf(fmaxf(dis * (a1.y + 2.f * s1.y) + sB[5], 0.f), sWo[5], acc);
    acc = fmaf(fmaxf(dis * (a1.z + 2.f * s1.z) + sB[6], 0.f), sWo[6], acc);
    acc = fmaf(fmaxf(dis * (a1.w + 2.f * s1.w) + sB[7], 0.f), sWo[7], acc);
    acc = fmaf(fmaxf(dis * (a2.x + 2.f * s2.x) + sB[8], 0.f), sWo[8], acc);
    acc = fmaf(fmaxf(dis * (a2.y + 2.f * s2.y) + sB[9], 0.f), sWo[9], acc);
    out[n] = acc;
}

extern "C" void kernel_launch(void* const* d_in, const int* in_sizes, int n_in,
                              void* d_out, int out_size) {
    const float* x    = (const float*)d_in[0];
    const int*   ei   = (const int*)  d_in[1];
    const float* Win  = (const float*)d_in[2];
    const float* bin  = (const float*)d_in[3];
    const float* W1   = (const float*)d_in[4];
    const float* b1   = (const float*)d_in[5];
    const float* W2   = (const float*)d_in[6];
    const float* b2   = (const float*)d_in[7];
    const float* Wout = (const float*)d_in[8];
    const float* bout = (const float*)d_in[9];
    float* out = (float*)d_out;

    void *cnt_p = nullptr, *hwA_p = nullptr, *hwB_p = nullptr;
    cudaGetSymbolAddress(&cnt_p, g_cnt);
    cudaGetSymbolAddress(&hwA_p, g_hwA);
    cudaGetSymbolAddress(&hwB_p, g_hwB);

    static cudaStream_t s1 = nullptr;
    static cudaEvent_t evFork = nullptr, evJoin = nullptr;
    if (s1 == nullptr) {
        cudaStreamCreateWithFlags(&s1, cudaStreamNonBlocking);
        cudaEventCreateWithFlags(&evFork, cudaEventDisableTiming);
        cudaEventCreateWithFlags(&evJoin, cudaEventDisableTiming);
    }

    const int TB = 256;
    int eb = (N_EDGES + TB - 1) / TB;
    int ib = (N_NODES / 2 + TB - 1) / TB;
    int sc = (N_NODES * 4 + TB - 1) / TB;
    int nb = (N_NODES + TB - 1) / TB;
    int gb = N_NODES / 8;

    // Fork: side stream runs the graph-independent input GEMV chain
    cudaEventRecord(evFork, 0);
    cudaStreamWaitEvent(s1, evFork, 0);
    k_input<<<ib, TB, 0, s1>>>(x, Win, bin, W1);
    cudaEventRecord(evJoin, s1);

    // Main stream: build buckets (concurrent with k_input)
    cudaMemsetAsync(cnt_p, 0, (size_t)N_NODES * sizeof(int));
    k_scatter<<<eb, TB>>>(ei);

    // Join, then scale + gather/finalize pairs
    cudaStreamWaitEvent(0, evJoin, 0);
    k_scale<<<sc, TB>>>();
    k_gath<<<gb, TB>>>((const float*)hwA_p);
    k_fin1<<<nb, TB>>>(b1, W2);
    k_gath<<<gb, TB>>>((const float*)hwB_p);
    k_fin2<<<nb, TB>>>(b2, Wout, bout, out);
}

// round 13
// speedup vs baseline: 1.5763x; 1.5763x over previous
#include <cuda_runtime.h>

#define N_NODES 320000
#define F_IN    128
#define L       10
#define CAP     80
#define N_EDGES 10240000
#define FULL    0xffffffffu

static __device__ int    g_cnt[N_NODES];
static __device__ float  g_dis[N_NODES];
static __device__ float4 g_hwA[(size_t)N_NODES * 4];   // 16-float padded rows (64B)
static __device__ float4 g_hwB[(size_t)N_NODES * 4];
static __device__ float4 g_agg[(size_t)N_NODES * 4];   // gather results
static __device__ int    g_csr[(size_t)N_NODES * CAP];

// ---------------------------------------------------------------------------
// 1) Bucket scatter (1 edge/thread, round-8 proven form)
// ---------------------------------------------------------------------------
__global__ void k_scatter(const int* __restrict__ ei) {
    int e = blockIdx.x * blockDim.x + threadIdx.x;
    if (e >= N_EDGES) return;
    int r = ei[e];
    int c = ei[N_EDGES + e];
    int pos = atomicAdd(&g_cnt[c], 1);
    if (pos < CAP) g_csr[(size_t)c * CAP + pos] = r;
}

// ---------------------------------------------------------------------------
// 2) Input, quad-cooperative (wavefront-cheap, overlapped with scatter):
//    hwA[n] = relu(x@Win + bin) @ W1   (UNSCALED)
//    4 lanes per 2 nodes; lane s reads 64B x-chunks -> 64B/wavefront.
//    Win in smem stride-11 (quad banks 4s apart: conflict-free, cross-quad
//    broadcast). W1 stride-16 zero-padded so pad quadrant = exact zeros.
// ---------------------------------------------------------------------------
__global__ void k_input(const float* __restrict__ x, const float* __restrict__ Win,
                        const float* __restrict__ bin, const float* __restrict__ W1) {
    __shared__ float sW[F_IN * 11];
    __shared__ float sW1p[L * 16];
    __shared__ float sB[L];
    int tid = threadIdx.x;
    for (int i = tid; i < F_IN * L; i += 256) {
        int k = i / L, j = i - k * L;
        sW[k * 11 + j] = Win[i];
    }
    for (int i = tid; i < L * 16; i += 256) {
        int l = i >> 4, j = i & 15;
        sW1p[i] = (j < L) ? W1[l * L + j] : 0.f;
    }
    if (tid < L) sB[tid] = bin[tid];
    __syncthreads();

    int s    = tid & 3;                 // sublane within quad
    int quad = tid >> 2;                // 0..63 within block
    int n0 = blockIdx.x * 128 + quad * 2;
    int n1 = n0 + 1;

    const float4* x0 = (const float4*)x + (size_t)n0 * 32;
    const float4* x1 = (const float4*)x + (size_t)n1 * 32;

    float acc0[L], acc1[L];
    #pragma unroll
    for (int j = 0; j < L; j++) { acc0[j] = 0.f; acc1[j] = 0.f; }

    #pragma unroll
    for (int q = 0; q < 8; q++) {
        float4 v0 = __ldg(&x0[q * 4 + s]);      // 64B chunk of row n0
        float4 v1 = __ldg(&x1[q * 4 + s]);      // 64B chunk of row n1
        float a0[4] = {v0.x, v0.y, v0.z, v0.w};
        float a1[4] = {v1.x, v1.y, v1.z, v1.w};
        int kb = (q * 16 + s * 4) * 11;
        #pragma unroll
        for (int u = 0; u < 4; u++) {
            const float* wr = &sW[kb + u * 11];
            #pragma unroll
            for (int j = 0; j < L; j++) {
                float w = wr[j];
                acc0[j] = fmaf(a0[u], w, acc0[j]);
                acc1[j] = fmaf(a1[u], w, acc1[j]);
            }
        }
    }

    // reduce across the 4 sublanes of the quad (lanes are consecutive)
    #pragma unroll
    for (int j = 0; j < L; j++) {
        acc0[j] += __shfl_xor_sync(FULL, acc0[j], 1);
        acc0[j] += __shfl_xor_sync(FULL, acc0[j], 2);
        acc1[j] += __shfl_xor_sync(FULL, acc1[j], 1);
        acc1[j] += __shfl_xor_sync(FULL, acc1[j], 2);
    }

    float h0[L], h1[L];
    #pragma unroll
    for (int j = 0; j < L; j++) {
        h0[j] = fmaxf(acc0[j] + sB[j], 0.f);
        h1[j] = fmaxf(acc1[j] + sB[j], 0.f);
    }

    // each sublane computes output quadrant s: t[j] for j = 4s..4s+3
    float4 t0 = make_float4(0.f, 0.f, 0.f, 0.f);
    float4 t1 = make_float4(0.f, 0.f, 0.f, 0.f);
    #pragma unroll
    for (int l = 0; l < L; l++) {
        const float* w = &sW1p[l * 16 + s * 4];
        t0.x = fmaf(h0[l], w[0], t0.x);
        t0.y = fmaf(h0[l], w[1], t0.y);
        t0.z = fmaf(h0[l], w[2], t0.z);
        t0.w = fmaf(h0[l], w[3], t0.w);
        t1.x = fmaf(h1[l], w[0], t1.x);
        t1.y = fmaf(h1[l], w[1], t1.y);
        t1.z = fmaf(h1[l], w[2], t1.z);
        t1.w = fmaf(h1[l], w[3], t1.w);
    }
    g_hwA[(size_t)n0 * 4 + s] = t0;             // coalesced 64B per node
    g_hwA[(size_t)n1 * 4 + s] = t1;
}

// ---------------------------------------------------------------------------
// 2b) Join: dis = rsqrt(deg+2); hwA *= dis
// ---------------------------------------------------------------------------
__global__ void k_scale() {
    int i = blockIdx.x * blockDim.x + threadIdx.x;      // float4 index
    if (i >= N_NODES * 4) return;
    int n = i >> 2;
    float dis = rsqrtf((float)g_cnt[n] + 2.0f);
    if ((i & 3) == 0) g_dis[n] = dis;
    float4 v = g_hwA[i];
    v.x *= dis; v.y *= dis; v.z *= dis; v.w *= dis;
    g_hwA[i] = v;
}

// ---------------------------------------------------------------------------
// 3) Pure gather (round-8 proven form): warp/node, 4 lanes/edge
// ---------------------------------------------------------------------------
__global__ void k_gath(const float4* __restrict__ src) {
    int n = (blockIdx.x * blockDim.x + threadIdx.x) >> 5;
    if (n >= N_NODES) return;
    int lane = threadIdx.x & 31;
    int sub  = lane >> 2;
    int c    = lane & 3;

    int cnt = g_cnt[n];
    if (cnt > CAP) cnt = CAP;
    const int* bucket = &g_csr[(size_t)n * CAP];

    float4 acc = make_float4(0.f, 0.f, 0.f, 0.f);
    for (int i = sub; i < cnt; i += 8) {
        int r = __ldg(&bucket[i]);
        float4 v = __ldg(&src[(size_t)r * 4 + c]);
        acc.x += v.x; acc.y += v.y; acc.z += v.z; acc.w += v.w;
    }
    #pragma unroll
    for (int s = 4; s < 32; s <<= 1) {
        acc.x += __shfl_xor_sync(FULL, acc.x, s);
        acc.y += __shfl_xor_sync(FULL, acc.y, s);
        acc.z += __shfl_xor_sync(FULL, acc.z, s);
        acc.w += __shfl_xor_sync(FULL, acc.w, s);
    }
    if (lane < 4) g_agg[(size_t)n * 4 + c] = acc;       // 64B coalesced
}

// ---------------------------------------------------------------------------
// 4) Finalize layer 1: h = relu(dis*(agg + 2*hwA) + b1);  hwB = dis*(h @ W2)
// ---------------------------------------------------------------------------
__global__ void k_fin1(const float* __restrict__ b1, const float* __restrict__ W2) {
    __shared__ float sW[L * L];
    __shared__ float sB[L];
    for (int i = threadIdx.x; i < L * L; i += blockDim.x) sW[i] = W2[i];
    if (threadIdx.x < L) sB[threadIdx.x] = b1[threadIdx.x];
    __syncthreads();

    int n = blockIdx.x * blockDim.x + threadIdx.x;
    if (n >= N_NODES) return;

    float dis = g_dis[n];
    const float4* ag = &g_agg[(size_t)n * 4];
    const float4* hw = &g_hwA[(size_t)n * 4];
    float4 a0 = ag[0], a1 = ag[1], a2 = ag[2];
    float4 s0 = hw[0], s1 = hw[1], s2 = hw[2];

    float h[L];
    h[0] = fmaxf(dis * (a0.x + 2.f * s0.x) + sB[0], 0.f);
    h[1] = fmaxf(dis * (a0.y + 2.f * s0.y) + sB[1], 0.f);
    h[2] = fmaxf(dis * (a0.z + 2.f * s0.z) + sB[2], 0.f);
    h[3] = fmaxf(dis * (a0.w + 2.f * s0.w) + sB[3], 0.f);
    h[4] = fmaxf(dis * (a1.x + 2.f * s1.x) + sB[4], 0.f);
    h[5] = fmaxf(dis * (a1.y + 2.f * s1.y) + sB[5], 0.f);
    h[6] = fmaxf(dis * (a1.z + 2.f * s1.z) + sB[6], 0.f);
    h[7] = fmaxf(dis * (a1.w + 2.f * s1.w) + sB[7], 0.f);
    h[8] = fmaxf(dis * (a2.x + 2.f * s2.x) + sB[8], 0.f);
    h[9] = fmaxf(dis * (a2.y + 2.f * s2.y) + sB[9], 0.f);

    float t[L];
    #pragma unroll
    for (int j = 0; j < L; j++) t[j] = 0.f;
    #pragma unroll
    for (int l = 0; l < L; l++) {
        #pragma unroll
        for (int j = 0; j < L; j++)
            t[j] = fmaf(h[l], sW[l * L + j], t[j]);
    }

    float4* o = &g_hwB[(size_t)n * 4];
    o[0] = make_float4(dis*t[0], dis*t[1], dis*t[2], dis*t[3]);
    o[1] = make_float4(dis*t[4], dis*t[5], dis*t[6], dis*t[7]);
    o[2] = make_float4(dis*t[8], dis*t[9], 0.f, 0.f);
    o[3] = make_float4(0.f, 0.f, 0.f, 0.f);
}

// ---------------------------------------------------------------------------
// 5) Finalize layer 2 + output
// ---------------------------------------------------------------------------
__global__ void k_fin2(const float* __restrict__ b2, const float* __restrict__ Wout,
                       const float* __restrict__ bout, float* __restrict__ out) {
    __shared__ float sWo[L];
    __shared__ float sB[L];
    __shared__ float sb0;
    if (threadIdx.x < L) { sWo[threadIdx.x] = Wout[threadIdx.x]; sB[threadIdx.x] = b2[threadIdx.x]; }
    if (threadIdx.x == 0) sb0 = bout[0];
    __syncthreads();

    int n = blockIdx.x * blockDim.x + threadIdx.x;
    if (n >= N_NODES) return;

    float dis = g_dis[n];
    const float4* ag = &g_agg[(size_t)n * 4];
    const float4* hw = &g_hwB[(size_t)n * 4];
    float4 a0 = ag[0], a1 = ag[1], a2 = ag[2];
    float4 s0 = hw[0], s1 = hw[1], s2 = hw[2];

    float acc = sb0;
    acc = fmaf(fmaxf(dis * (a0.x + 2.f * s0.x) + sB[0], 0.f), sWo[0], acc);
    acc = fmaf(fmaxf(dis * (a0.y + 2.f * s0.y) + sB[1], 0.f), sWo[1], acc);
    acc = fmaf(fmaxf(dis * (a0.z + 2.f * s0.z) + sB[2], 0.f), sWo[2], acc);
    acc = fmaf(fmaxf(dis * (a0.w + 2.f * s0.w) + sB[3], 0.f), sWo[3], acc);
    acc = fmaf(fmaxf(dis * (a1.x + 2.f * s1.x) + sB[4], 0.f), sWo[4], acc);
    acc = fmaf(fmaxf(dis * (a1.y + 2.f * s1.y) + sB[5], 0.f), sWo[5], acc);
    acc = fmaf(fmaxf(dis * (a1.z + 2.f * s1.z) + sB[6], 0.f), sWo[6], acc);
    acc = fmaf(fmaxf(dis * (a1.w + 2.f * s1.w) + sB[7], 0.f), sWo[7], acc);
    acc = fmaf(fmaxf(dis * (a2.x + 2.f * s2.x) + sB[8], 0.f), sWo[8], acc);
    acc = fmaf(fmaxf(dis * (a2.y + 2.f * s2.y) + sB[9], 0.f), sWo[9], acc);
    out[n] = acc;
}

extern "C" void kernel_launch(void* const* d_in, const int* in_sizes, int n_in,
                              void* d_out, int out_size) {
    const float* x    = (const float*)d_in[0];
    const int*   ei   = (const int*)  d_in[1];
    const float* Win  = (const float*)d_in[2];
    const float* bin  = (const float*)d_in[3];
    const float* W1   = (const float*)d_in[4];
    const float* b1   = (const float*)d_in[5];
    const float* W2   = (const float*)d_in[6];
    const float* b2   = (const float*)d_in[7];
    const float* Wout = (const float*)d_in[8];
    const float* bout = (const float*)d_in[9];
    float* out = (float*)d_out;

    void *cnt_p = nullptr, *hwA_p = nullptr, *hwB_p = nullptr;
    cudaGetSymbolAddress(&cnt_p, g_cnt);
    cudaGetSymbolAddress(&hwA_p, g_hwA);
    cudaGetSymbolAddress(&hwB_p, g_hwB);

    static cudaStream_t s1 = nullptr;
    static cudaEvent_t evFork = nullptr, evJoin = nullptr;
    if (s1 == nullptr) {
        cudaStreamCreateWithFlags(&s1, cudaStreamNonBlocking);
        cudaEventCreateWithFlags(&evFork, cudaEventDisableTiming);
        cudaEventCreateWithFlags(&evJoin, cudaEventDisableTiming);
    }

    const int TB = 256;
    int eb = (N_EDGES + TB - 1) / TB;
    int ib = N_NODES / 128;                  // 128 nodes per 256-thread block
    int sc = (N_NODES * 4 + TB - 1) / TB;
    int nb = (N_NODES + TB - 1) / TB;
    int gb = N_NODES / 8;

    // Fork: side stream runs the graph-independent input GEMV chain
    cudaEventRecord(evFork, 0);
    cudaStreamWaitEvent(s1, evFork, 0);
    k_input<<<ib, TB, 0, s1>>>(x, Win, bin, W1);
    cudaEventRecord(evJoin, s1);

    // Main stream: build buckets (concurrent with k_input)
    cudaMemsetAsync(cnt_p, 0, (size_t)N_NODES * sizeof(int));
    k_scatter<<<eb, TB>>>(ei);

    // Join, then scale + gather/finalize pairs
    cudaStreamWaitEvent(0, evJoin, 0);
    k_scale<<<sc, TB>>>();
    k_gath<<<gb, TB>>>((const float4*)hwA_p);
    k_fin1<<<nb, TB>>>(b1, W2);
    k_gath<<<gb, TB>>>((const float4*)hwB_p);
    k_fin2<<<nb, TB>>>(b2, Wout, bout, out);
}